// round 1
// baseline (speedup 1.0000x reference)
#include <cuda_runtime.h>
#include <cuda_bf16.h>
#include <math.h>

// LRML memory-network scoring.
// Inputs (metadata order):
//  0: user_ids  int32  [B]
//  1: item_ids  int32  [B]
//  2: user_emb  f32    [U, 32]
//  3: item_emb  f32    [I, 32]
//  4: W_att     f32    [10, 32]
//  5: memory    f32    [10, 32]
// Output: f32 [B]  = -sum((ue + rel - ie)^2)
//
// One warp per batch element; lane == embedding dimension (D = 32).

#define D 32
#define M 10
#define WARPS_PER_BLOCK 8
#define THREADS_PER_BLOCK (WARPS_PER_BLOCK * 32)

__global__ __launch_bounds__(THREADS_PER_BLOCK)
void LRML_90804198572513_kernel(const int* __restrict__ user_ids,
                                const int* __restrict__ item_ids,
                                const float* __restrict__ user_emb,
                                const float* __restrict__ item_emb,
                                const float* __restrict__ W_att,
                                const float* __restrict__ memory,
                                float* __restrict__ out,
                                int B) {
    __shared__ float sW[M * D];
    __shared__ float sMem[M * D];

    // Stage tiny attention weights + memory slots into shared memory.
    for (int i = threadIdx.x; i < M * D; i += THREADS_PER_BLOCK) {
        sW[i]   = W_att[i];
        sMem[i] = memory[i];
    }
    __syncthreads();

    const int lane = threadIdx.x & 31;
    const int warp = threadIdx.x >> 5;
    const int b = blockIdx.x * WARPS_PER_BLOCK + warp;
    if (b >= B) return;

    const int uid = user_ids[b];
    const int iid = item_ids[b];

    // Coalesced 128B row gathers: lane d loads dimension d.
    float ue = __ldg(&user_emb[(size_t)uid * D + lane]);
    float ie = __ldg(&item_emb[(size_t)iid * D + lane]);

    // L2 norms of both rows (butterfly reduce; all lanes end with the sum).
    float nu = ue * ue;
    float ni = ie * ie;
    #pragma unroll
    for (int o = 16; o > 0; o >>= 1) {
        nu += __shfl_xor_sync(0xFFFFFFFFu, nu, o);
        ni += __shfl_xor_sync(0xFFFFFFFFu, ni, o);
    }
    // renorm: e * (1 / max(||e||, 1))
    ue *= 1.0f / fmaxf(sqrtf(nu), 1.0f);
    ie *= 1.0f / fmaxf(sqrtf(ni), 1.0f);

    const float joint = ue * ie;

    // scores[m] = sum_d joint[d] * W_att[m][d]  — 10 butterfly reductions.
    float s[M];
    #pragma unroll
    for (int m = 0; m < M; m++) {
        float v = joint * sW[m * D + lane];
        #pragma unroll
        for (int o = 16; o > 0; o >>= 1)
            v += __shfl_xor_sync(0xFFFFFFFFu, v, o);
        s[m] = v;  // every lane holds the full score vector
    }

    // Softmax over M=10 (numerically stable, redundantly per lane).
    float mx = s[0];
    #pragma unroll
    for (int m = 1; m < M; m++) mx = fmaxf(mx, s[m]);
    float sum = 0.0f;
    #pragma unroll
    for (int m = 0; m < M; m++) {
        s[m] = __expf(s[m] - mx);
        sum += s[m];
    }
    const float inv = 1.0f / sum;

    // rel[d] = sum_m softmax[m] * memory[m][d]
    float rel = 0.0f;
    #pragma unroll
    for (int m = 0; m < M; m++)
        rel = fmaf(s[m] * inv, sMem[m * D + lane], rel);

    // dist = sum_d (ue + rel - ie)^2 ; out = -dist
    float d = ue + rel - ie;
    d = d * d;
    #pragma unroll
    for (int o = 16; o > 0; o >>= 1)
        d += __shfl_xor_sync(0xFFFFFFFFu, d, o);

    if (lane == 0) out[b] = -d;
}

extern "C" void kernel_launch(void* const* d_in, const int* in_sizes, int n_in,
                              void* d_out, int out_size) {
    const int*   user_ids = (const int*)  d_in[0];
    const int*   item_ids = (const int*)  d_in[1];
    const float* user_emb = (const float*)d_in[2];
    const float* item_emb = (const float*)d_in[3];
    const float* W_att    = (const float*)d_in[4];
    const float* memory   = (const float*)d_in[5];
    float* out = (float*)d_out;

    const int B = in_sizes[0];
    const int grid = (B + WARPS_PER_BLOCK - 1) / WARPS_PER_BLOCK;
    LRML_90804198572513_kernel<<<grid, THREADS_PER_BLOCK>>>(
        user_ids, item_ids, user_emb, item_emb, W_att, memory, out, B);
}

// round 2
// speedup vs baseline: 1.5351x; 1.5351x over previous
#include <cuda_runtime.h>
#include <cuda_bf16.h>
#include <math.h>

// LRML memory-network scoring, 4-lanes-per-element layout.
//  0: user_ids  int32  [B]
//  1: item_ids  int32  [B]
//  2: user_emb  f32    [U, 32]
//  3: item_emb  f32    [I, 32]
//  4: W_att     f32    [10, 32]
//  5: memory    f32    [10, 32]
// Output: f32 [B] = -sum((ue + rel - ie)^2)
//
// Each element is handled by a group of 4 lanes; lane `sub` owns dims
// [sub*8, sub*8+8) as two float4s. One warp processes 8 elements, so every
// warp-wide SHFL/LDS amortizes over 8 outputs.

#define M 10
#define THREADS_PER_BLOCK 128   // 4 warps -> 32 elements per block

__global__ __launch_bounds__(THREADS_PER_BLOCK)
void LRML_90804198572513_kernel(const int* __restrict__ user_ids,
                                const int* __restrict__ item_ids,
                                const float* __restrict__ user_emb,
                                const float* __restrict__ item_emb,
                                const float* __restrict__ W_att,
                                const float* __restrict__ memory,
                                float* __restrict__ out,
                                int B) {
    __shared__ float4 sW[M][8];   // W_att rows as 8 float4s
    __shared__ float4 sM[M][8];   // memory rows as 8 float4s

    for (int i = threadIdx.x; i < M * 8; i += THREADS_PER_BLOCK) {
        ((float4*)sW)[i] = ((const float4*)W_att)[i];
        ((float4*)sM)[i] = ((const float4*)memory)[i];
    }
    __syncthreads();

    const int lane = threadIdx.x & 31;
    const int warp = threadIdx.x >> 5;
    const int sub  = lane & 3;    // 8-dim slice owner within the group
    const int eg   = lane >> 2;   // element index within warp (0..7)
    const int b = ((blockIdx.x * (THREADS_PER_BLOCK / 32) + warp) << 3) + eg;
    if (b >= B) return;

    const int uid = user_ids[b];
    const int iid = item_ids[b];

    // Coalesced row gathers: lanes 0..3 of a group cover one full 128B row.
    const float4* up = (const float4*)(user_emb + (size_t)uid * 32) + sub * 2;
    const float4* ip = (const float4*)(item_emb + (size_t)iid * 32) + sub * 2;
    const float4 u0 = up[0], u1 = up[1];
    const float4 i0 = ip[0], i1 = ip[1];

    // Partial squared norms over this lane's 8 dims.
    float nu = u0.x*u0.x + u0.y*u0.y + u0.z*u0.z + u0.w*u0.w
             + u1.x*u1.x + u1.y*u1.y + u1.z*u1.z + u1.w*u1.w;
    float ni = i0.x*i0.x + i0.y*i0.y + i0.z*i0.z + i0.w*i0.w
             + i1.x*i1.x + i1.y*i1.y + i1.z*i1.z + i1.w*i1.w;
    // Reduce within the 4-lane group (offsets 1 and 2 stay inside the group).
    nu += __shfl_xor_sync(0xFFFFFFFFu, nu, 1);
    nu += __shfl_xor_sync(0xFFFFFFFFu, nu, 2);
    ni += __shfl_xor_sync(0xFFFFFFFFu, ni, 1);
    ni += __shfl_xor_sync(0xFFFFFFFFu, ni, 2);

    // scale = 1 / max(||e||, 1) = min(rsqrt(n), 1)  (n=0 -> inf -> 1, correct)
    const float su = fminf(rsqrtf(nu), 1.0f);
    const float si = fminf(rsqrtf(ni), 1.0f);

    // Renormalized vectors (needed for the final distance).
    float4 ur0, ur1, ir0, ir1;
    ur0.x = u0.x*su; ur0.y = u0.y*su; ur0.z = u0.z*su; ur0.w = u0.w*su;
    ur1.x = u1.x*su; ur1.y = u1.y*su; ur1.z = u1.z*su; ur1.w = u1.w*su;
    ir0.x = i0.x*si; ir0.y = i0.y*si; ir0.z = i0.z*si; ir0.w = i0.w*si;
    ir1.x = i1.x*si; ir1.y = i1.y*si; ir1.z = i1.z*si; ir1.w = i1.w*si;

    // joint = ue_r * ie_r (elementwise)
    float4 j0, j1;
    j0.x = ur0.x*ir0.x; j0.y = ur0.y*ir0.y; j0.z = ur0.z*ir0.z; j0.w = ur0.w*ir0.w;
    j1.x = ur1.x*ir1.x; j1.y = ur1.y*ir1.y; j1.z = ur1.z*ir1.z; j1.w = ur1.w*ir1.w;

    // scores[m] = <joint, W_att[m]> — partials per lane, then 2 butterfly stages.
    float s[M];
    #pragma unroll
    for (int m = 0; m < M; m++) {
        const float4 w0 = sW[m][sub * 2];
        const float4 w1 = sW[m][sub * 2 + 1];
        s[m] = j0.x*w0.x + j0.y*w0.y + j0.z*w0.z + j0.w*w0.w
             + j1.x*w1.x + j1.y*w1.y + j1.z*w1.z + j1.w*w1.w;
    }
    #pragma unroll
    for (int m = 0; m < M; m++) s[m] += __shfl_xor_sync(0xFFFFFFFFu, s[m], 1);
    #pragma unroll
    for (int m = 0; m < M; m++) s[m] += __shfl_xor_sync(0xFFFFFFFFu, s[m], 2);

    // Softmax over M=10 (redundant in each lane of the group — cheap).
    float mx = s[0];
    #pragma unroll
    for (int m = 1; m < M; m++) mx = fmaxf(mx, s[m]);
    float sum = 0.0f;
    #pragma unroll
    for (int m = 0; m < M; m++) { s[m] = __expf(s[m] - mx); sum += s[m]; }
    const float inv = 1.0f / sum;

    // rel[d] = sum_m p[m] * memory[m][d] for this lane's 8 dims.
    float4 r0 = make_float4(0.f, 0.f, 0.f, 0.f);
    float4 r1 = make_float4(0.f, 0.f, 0.f, 0.f);
    #pragma unroll
    for (int m = 0; m < M; m++) {
        const float p = s[m] * inv;
        const float4 m0 = sM[m][sub * 2];
        const float4 m1 = sM[m][sub * 2 + 1];
        r0.x = fmaf(p, m0.x, r0.x); r0.y = fmaf(p, m0.y, r0.y);
        r0.z = fmaf(p, m0.z, r0.z); r0.w = fmaf(p, m0.w, r0.w);
        r1.x = fmaf(p, m1.x, r1.x); r1.y = fmaf(p, m1.y, r1.y);
        r1.z = fmaf(p, m1.z, r1.z); r1.w = fmaf(p, m1.w, r1.w);
    }

    // dist partial over this lane's 8 dims, reduce within group.
    float dx, d = 0.0f;
    dx = ur0.x + r0.x - ir0.x; d = fmaf(dx, dx, d);
    dx = ur0.y + r0.y - ir0.y; d = fmaf(dx, dx, d);
    dx = ur0.z + r0.z - ir0.z; d = fmaf(dx, dx, d);
    dx = ur0.w + r0.w - ir0.w; d = fmaf(dx, dx, d);
    dx = ur1.x + r1.x - ir1.x; d = fmaf(dx, dx, d);
    dx = ur1.y + r1.y - ir1.y; d = fmaf(dx, dx, d);
    dx = ur1.z + r1.z - ir1.z; d = fmaf(dx, dx, d);
    dx = ur1.w + r1.w - ir1.w; d = fmaf(dx, dx, d);
    d += __shfl_xor_sync(0xFFFFFFFFu, d, 1);
    d += __shfl_xor_sync(0xFFFFFFFFu, d, 2);

    if (sub == 0) out[b] = -d;
}

extern "C" void kernel_launch(void* const* d_in, const int* in_sizes, int n_in,
                              void* d_out, int out_size) {
    const int*   user_ids = (const int*)  d_in[0];
    const int*   item_ids = (const int*)  d_in[1];
    const float* user_emb = (const float*)d_in[2];
    const float* item_emb = (const float*)d_in[3];
    const float* W_att    = (const float*)d_in[4];
    const float* memory   = (const float*)d_in[5];
    float* out = (float*)d_out;

    const int B = in_sizes[0];
    const int elems_per_block = (THREADS_PER_BLOCK / 32) * 8;  // 32
    const int grid = (B + elems_per_block - 1) / elems_per_block;
    LRML_90804198572513_kernel<<<grid, THREADS_PER_BLOCK>>>(
        user_ids, item_ids, user_emb, item_emb, W_att, memory, out, B);
}